// round 8
// baseline (speedup 1.0000x reference)
#include <cuda_runtime.h>
#include <cuda_fp16.h>

#define NODES 50000
#define NEDGES 800000
#define F 128

// ---------------- scratch (device globals; no runtime allocation) ------------
__device__ int    g_cnt[NODES];
__device__ int    g_off[NODES + 1];
__device__ int    g_cur[NODES];
__device__ int    g_csr[NEDGES];
__device__ int    g_part[64];
__device__ float  g_h1[NODES * F];
__device__ __half g_xh[NODES * F];       // fp16 copy of x (gather path)
__device__ __half g_h1h[NODES * F];      // fp16 copy of h1 (gather path)
__device__ int    g_is64;

// ---------------- index dtype detection --------------------------------------
__global__ void detect_kernel(const int* __restrict__ p) {
    __shared__ int ok;
    if (threadIdx.x == 0) ok = 1;
    __syncthreads();
    if (p[2 * threadIdx.x + 1] != 0) atomicAnd(&ok, 0);
    __syncthreads();
    if (threadIdx.x == 0) g_is64 = ok;
}

__device__ __forceinline__ int load_idx(const void* __restrict__ p, long i, int is64) {
    if (is64) return (int)((const long long*)p)[i];
    return ((const int*)p)[i];
}

// ---------------- zero fill (two arrays in one launch) ------------------------
__global__ void zero2_kernel(int* __restrict__ a, int* __restrict__ b, int n4) {
    int i = blockIdx.x * blockDim.x + threadIdx.x;
    int4 z = make_int4(0, 0, 0, 0);
    for (; i < n4; i += gridDim.x * blockDim.x) {
        ((int4*)a)[i] = z;
        ((int4*)b)[i] = z;
    }
}

// ---------------- fp32 -> fp16 conversion ------------------------------------
__global__ void f2h_kernel(const float* __restrict__ src, __half* __restrict__ dst, int n4) {
    int i = blockIdx.x * blockDim.x + threadIdx.x;
    for (; i < n4; i += gridDim.x * blockDim.x) {
        float4 v = ((const float4*)src)[i];
        __half2 a = __floats2half2_rn(v.x, v.y);
        __half2 b = __floats2half2_rn(v.z, v.w);
        uint2 u;
        u.x = *(unsigned*)&a;
        u.y = *(unsigned*)&b;
        ((uint2*)dst)[i] = u;
    }
}

// ---------------- CSR build --------------------------------------------------
__global__ void count_kernel(const void* __restrict__ ei, int* __restrict__ cnt, int nE) {
    int i = blockIdx.x * blockDim.x + threadIdx.x;
    int is64 = g_is64;
    if (i < nE) {
        int d = load_idx(ei, (long)nE + i, is64);
        if ((unsigned)d < NODES) atomicAdd(&cnt[d], 1);
    }
}

// ---- 3-phase scan: block scans -> serial scan of partials -> add-back -------
__global__ __launch_bounds__(1024) void scan1_kernel(
    const int* __restrict__ cnt, int* __restrict__ off, int* __restrict__ part, int n)
{
    __shared__ int wsum[32];
    int tid = threadIdx.x, lane = tid & 31, wid = tid >> 5;
    int g = blockIdx.x * 1024 + tid;
    int v = (g < n) ? cnt[g] : 0;
    int s = v;
#pragma unroll
    for (int d = 1; d < 32; d <<= 1) {
        int t = __shfl_up_sync(0xffffffffu, s, d);
        if (lane >= d) s += t;
    }
    if (lane == 31) wsum[wid] = s;
    __syncthreads();
    if (wid == 0) {
        int ws = wsum[lane];
#pragma unroll
        for (int d = 1; d < 32; d <<= 1) {
            int t = __shfl_up_sync(0xffffffffu, ws, d);
            if (lane >= d) ws += t;
        }
        wsum[lane] = ws;
    }
    __syncthreads();
    int base = wid ? wsum[wid - 1] : 0;
    if (g < n) off[g] = base + s - v;       // block-local exclusive
    if (tid == 1023) part[blockIdx.x] = wsum[31];
}

__global__ void scan2_kernel(int* __restrict__ part, int nb) {
    if (threadIdx.x == 0) {
        int run = 0;
        for (int i = 0; i < nb; i++) { int t = part[i]; part[i] = run; run += t; }
        part[nb] = run;
    }
}

__global__ __launch_bounds__(1024) void scan3_kernel(
    int* __restrict__ off, const int* __restrict__ part, int n, int nb)
{
    int g = blockIdx.x * 1024 + threadIdx.x;
    if (g < n) off[g] += part[blockIdx.x];
    if (g == 0) off[n] = part[nb];
}

__global__ void fill_kernel(const void* __restrict__ ei,
                            const int* __restrict__ off, int* __restrict__ cur,
                            int* __restrict__ csr, int nE)
{
    int i = blockIdx.x * blockDim.x + threadIdx.x;
    int is64 = g_is64;
    if (i < nE) {
        int s = load_idx(ei, i, is64);
        int d = load_idx(ei, (long)nE + i, is64);
        if ((unsigned)s < NODES && (unsigned)d < NODES) {
            int pos = off[d] + atomicAdd(&cur[d], 1);
            csr[pos] = s;
        }
    }
}

// ---------------- fused SAGE layer -------------------------------------------
// Phase A: gather neighbor means (fp16 reads, fp32 accumulate) + fp32 root rows
// into smem. Phase B: dual-GEMM with packed f32x2 FMA (FFMA2).
// FUSE_FC=0: writes fp32 out + fp16 outh.  FUSE_FC=1: fused 128->2 FC head.
template <int FUSE_FC>
__global__ __launch_bounds__(256) void sage_layer_kernel(
    const int* __restrict__ off, const int* __restrict__ csr,
    const float* __restrict__ feat, const __half* __restrict__ feath,
    const float* __restrict__ Wl, const float* __restrict__ Wr,
    const float* __restrict__ bias,
    const float* __restrict__ Wfc, const float* __restrict__ bfc,
    float* __restrict__ out, __half* __restrict__ outh, int n)
{
    extern __shared__ float smem[];
    float* sAgg  = smem;                    // [64][128]
    float* sRoot = smem + 64 * F;           // [64][128]
    float* sWl   = smem + 2 * 64 * F;       // [32][128]
    float* sWr   = sWl + 32 * F;            // [32][128]
    float* sFc   = sWr + 32 * F;            // [256]

    int tid  = threadIdx.x;
    int w    = tid >> 5;
    int lane = tid & 31;
    int rowBase = blockIdx.x * 64;

    // ---------- Phase A: gather (warp w handles rows w*8 .. w*8+7) ----------
    for (int r = 0; r < 8; r++) {
        int rl = w * 8 + r;
        int row = rowBase + rl;
        float4 a0 = make_float4(0.f, 0.f, 0.f, 0.f);
        float4 a1 = make_float4(0.f, 0.f, 0.f, 0.f);
        float4 a2 = make_float4(0.f, 0.f, 0.f, 0.f);
        float4 a3 = make_float4(0.f, 0.f, 0.f, 0.f);
        float inv = 0.f;
        if (row < n) {
            int o0 = __ldg(&off[row]), o1 = __ldg(&off[row + 1]);
            int e = o0;
            for (; e + 3 < o1; e += 4) {
                int i0 = __ldg(&csr[e]);
                int i1 = __ldg(&csr[e + 1]);
                int i2 = __ldg(&csr[e + 2]);
                int i3 = __ldg(&csr[e + 3]);
                uint2 u0 = ((const uint2*)(feath + (long)i0 * F))[lane];
                uint2 u1 = ((const uint2*)(feath + (long)i1 * F))[lane];
                uint2 u2 = ((const uint2*)(feath + (long)i2 * F))[lane];
                uint2 u3 = ((const uint2*)(feath + (long)i3 * F))[lane];
                float2 f;
                f = __half22float2(*(__half2*)&u0.x); a0.x += f.x; a0.y += f.y;
                f = __half22float2(*(__half2*)&u0.y); a0.z += f.x; a0.w += f.y;
                f = __half22float2(*(__half2*)&u1.x); a1.x += f.x; a1.y += f.y;
                f = __half22float2(*(__half2*)&u1.y); a1.z += f.x; a1.w += f.y;
                f = __half22float2(*(__half2*)&u2.x); a2.x += f.x; a2.y += f.y;
                f = __half22float2(*(__half2*)&u2.y); a2.z += f.x; a2.w += f.y;
                f = __half22float2(*(__half2*)&u3.x); a3.x += f.x; a3.y += f.y;
                f = __half22float2(*(__half2*)&u3.y); a3.z += f.x; a3.w += f.y;
            }
            for (; e < o1; e++) {
                int i0 = __ldg(&csr[e]);
                uint2 u0 = ((const uint2*)(feath + (long)i0 * F))[lane];
                float2 f;
                f = __half22float2(*(__half2*)&u0.x); a0.x += f.x; a0.y += f.y;
                f = __half22float2(*(__half2*)&u0.y); a0.z += f.x; a0.w += f.y;
            }
            inv = 1.0f / fmaxf((float)(o1 - o0), 1.0f);
        }
        float4 o;
        o.x = (a0.x + a1.x + a2.x + a3.x) * inv;
        o.y = (a0.y + a1.y + a2.y + a3.y) * inv;
        o.z = (a0.z + a1.z + a2.z + a3.z) * inv;
        o.w = (a0.w + a1.w + a2.w + a3.w) * inv;
        ((float4*)&sAgg[rl * F])[lane] = o;
    }
    // root rows: fp32, 64 rows x 32 float4, 8 per thread
#pragma unroll
    for (int i = 0; i < 8; i++) {
        int idx = tid + 256 * i;
        int row = rowBase + (idx >> 5);
        int c = idx & 31;
        float4 v = make_float4(0.f, 0.f, 0.f, 0.f);
        if (row < n) v = ((const float4*)(feat + (long)row * F))[c];
        ((float4*)sRoot)[idx] = v;
    }
    if (FUSE_FC) sFc[tid] = Wfc[tid];

    // ---------- Phase B: dual-GEMM with FFMA2 --------------------------------
    unsigned long long acc01[8], acc23[8];
#pragma unroll
    for (int r = 0; r < 8; r++) { acc01[r] = 0ull; acc23[r] = 0ull; }

    for (int kt = 0; kt < 4; kt++) {
        __syncthreads();
        const float4* wl4 = (const float4*)(Wl + kt * 32 * F);
        const float4* wr4 = (const float4*)(Wr + kt * 32 * F);
#pragma unroll
        for (int i = 0; i < 4; i++) {
            ((float4*)sWl)[tid + 256 * i] = wl4[tid + 256 * i];
            ((float4*)sWr)[tid + 256 * i] = wr4[tid + 256 * i];
        }
        __syncthreads();
#pragma unroll
        for (int k = 0; k < 32; k++) {
            ulonglong2 wl = ((const ulonglong2*)(sWl + k * F))[lane];
            ulonglong2 wr = ((const ulonglong2*)(sWr + k * F))[lane];
#pragma unroll
            for (int r = 0; r < 8; r++) {
                int rl = w * 8 + r;
                unsigned ai = __float_as_uint(sAgg[rl * F + kt * 32 + k]);
                unsigned xi = __float_as_uint(sRoot[rl * F + kt * 32 + k]);
                unsigned long long a2, x2;
                asm("mov.b64 %0, {%1, %1};" : "=l"(a2) : "r"(ai));
                asm("mov.b64 %0, {%1, %1};" : "=l"(x2) : "r"(xi));
                asm("fma.rn.f32x2 %0, %1, %2, %0;" : "+l"(acc01[r]) : "l"(a2), "l"(wl.x));
                asm("fma.rn.f32x2 %0, %1, %2, %0;" : "+l"(acc23[r]) : "l"(a2), "l"(wl.y));
                asm("fma.rn.f32x2 %0, %1, %2, %0;" : "+l"(acc01[r]) : "l"(x2), "l"(wr.x));
                asm("fma.rn.f32x2 %0, %1, %2, %0;" : "+l"(acc23[r]) : "l"(x2), "l"(wr.y));
            }
        }
    }

    // ---------- epilogue -----------------------------------------------------
    float4 bv = ((const float4*)bias)[lane];
#pragma unroll
    for (int r = 0; r < 8; r++) {
        int row = rowBase + w * 8 + r;
        unsigned u0, u1, u2, u3;
        asm("mov.b64 {%0, %1}, %2;" : "=r"(u0), "=r"(u1) : "l"(acc01[r]));
        asm("mov.b64 {%0, %1}, %2;" : "=r"(u2), "=r"(u3) : "l"(acc23[r]));
        float h0 = fmaxf(__uint_as_float(u0) + bv.x, 0.f);
        float h1 = fmaxf(__uint_as_float(u1) + bv.y, 0.f);
        float h2 = fmaxf(__uint_as_float(u2) + bv.z, 0.f);
        float h3 = fmaxf(__uint_as_float(u3) + bv.w, 0.f);
        if (!FUSE_FC) {
            if (row < n) {
                float4 o; o.x = h0; o.y = h1; o.z = h2; o.w = h3;
                ((float4*)(out + (long)row * F))[lane] = o;
                __half2 p01 = __floats2half2_rn(h0, h1);
                __half2 p23 = __floats2half2_rn(h2, h3);
                uint2 st;
                st.x = *(unsigned*)&p01;
                st.y = *(unsigned*)&p23;
                ((uint2*)(outh + (long)row * F))[lane] = st;
            }
        } else {
            int c0 = lane * 4;
            float p0 = h0 * sFc[(c0 + 0) * 2 + 0] + h1 * sFc[(c0 + 1) * 2 + 0]
                     + h2 * sFc[(c0 + 2) * 2 + 0] + h3 * sFc[(c0 + 3) * 2 + 0];
            float p1 = h0 * sFc[(c0 + 0) * 2 + 1] + h1 * sFc[(c0 + 1) * 2 + 1]
                     + h2 * sFc[(c0 + 2) * 2 + 1] + h3 * sFc[(c0 + 3) * 2 + 1];
#pragma unroll
            for (int d = 16; d > 0; d >>= 1) {
                p0 += __shfl_xor_sync(0xFFFFFFFFu, p0, d);
                p1 += __shfl_xor_sync(0xFFFFFFFFu, p1, d);
            }
            if (lane == 0 && row < n) {
                float2 o;
                o.x = p0 + __ldg(&bfc[0]);
                o.y = p1 + __ldg(&bfc[1]);
                ((float2*)out)[row] = o;
            }
        }
    }
}

// -----------------------------------------------------------------------------
extern "C" void kernel_launch(void* const* d_in, const int* in_sizes, int n_in,
                              void* d_out, int out_size)
{
    const float* x    = (const float*)d_in[0];
    const void*  ei   = d_in[1];                 // int32 or int64, auto-detected
    const float* W1l  = (const float*)d_in[2];
    const float* W1r  = (const float*)d_in[3];
    const float* b1   = (const float*)d_in[4];
    const float* W2l  = (const float*)d_in[5];
    const float* W2r  = (const float*)d_in[6];
    const float* b2   = (const float*)d_in[7];
    const float* Wfc  = (const float*)d_in[8];
    const float* bfc  = (const float*)d_in[9];
    float*       out  = (float*)d_out;

    int n  = in_sizes[0] / F;       // 50000
    int nE = in_sizes[1] / 2;       // 800000

    int *cnt, *off, *cur, *csr, *part;
    float *h1;
    __half *xh, *h1h;
    cudaGetSymbolAddress((void**)&cnt,  g_cnt);
    cudaGetSymbolAddress((void**)&off,  g_off);
    cudaGetSymbolAddress((void**)&cur,  g_cur);
    cudaGetSymbolAddress((void**)&csr,  g_csr);
    cudaGetSymbolAddress((void**)&part, g_part);
    cudaGetSymbolAddress((void**)&h1,   g_h1);
    cudaGetSymbolAddress((void**)&xh,   g_xh);
    cudaGetSymbolAddress((void**)&h1h,  g_h1h);

    const int SMEM = (64 * F * 2 + 32 * F * 2 + 256) * 4;   // 99,328 bytes
    cudaFuncSetAttribute(sage_layer_kernel<0>,
                         cudaFuncAttributeMaxDynamicSharedMemorySize, SMEM);
    cudaFuncSetAttribute(sage_layer_kernel<1>,
                         cudaFuncAttributeMaxDynamicSharedMemorySize, SMEM);

    detect_kernel<<<1, 256>>>((const int*)ei);

    // ---- CSR build (once, reused for both layers) ----
    int nb = (n + 1023) / 1024;                 // 49
    zero2_kernel<<<32, 256>>>(cnt, cur, (n + 3) / 4);
    count_kernel<<<(nE + 255) / 256, 256>>>(ei, cnt, nE);
    scan1_kernel<<<nb, 1024>>>(cnt, off, part, n);
    scan2_kernel<<<1, 32>>>(part, nb);
    scan3_kernel<<<nb, 1024>>>(off, part, n, nb);
    f2h_kernel<<<512, 256>>>(x, xh, n * F / 4);
    fill_kernel<<<(nE + 255) / 256, 256>>>(ei, off, cur, csr, nE);

    int blocks = (n + 63) / 64;

    // ---- layer 1 (writes fp32 h1 + fp16 h1h) ----
    sage_layer_kernel<0><<<blocks, 256, SMEM>>>(
        off, csr, x, xh, W1l, W1r, b1, (const float*)0, (const float*)0, h1, h1h, n);

    // ---- layer 2 + FC head fused (writes logits) ----
    sage_layer_kernel<1><<<blocks, 256, SMEM>>>(
        off, csr, h1, h1h, W2l, W2r, b2, Wfc, bfc, out, (__half*)0, n);
}

// round 9
// speedup vs baseline: 1.5008x; 1.5008x over previous
#include <cuda_runtime.h>

#define NODES 50000
#define NEDGES 800000
#define F 128

// ---------------- scratch (device globals; no runtime allocation) ------------
__device__ int   g_cnt[NODES];
__device__ int   g_off[NODES + 1];
__device__ int   g_cur[NODES];
__device__ int   g_csr[NEDGES];
__device__ int   g_part[64];
__device__ float g_h1[NODES * F];
__device__ int   g_is64;

// ---------------- index dtype detection --------------------------------------
__global__ void detect_kernel(const int* __restrict__ p) {
    __shared__ int ok;
    if (threadIdx.x == 0) ok = 1;
    __syncthreads();
    if (p[2 * threadIdx.x + 1] != 0) atomicAnd(&ok, 0);
    __syncthreads();
    if (threadIdx.x == 0) g_is64 = ok;
}

__device__ __forceinline__ int load_idx(const void* __restrict__ p, long i, int is64) {
    if (is64) return (int)((const long long*)p)[i];
    return ((const int*)p)[i];
}

// ---------------- zero fill (two arrays in one launch) ------------------------
__global__ void zero2_kernel(int* __restrict__ a, int* __restrict__ b, int n4) {
    int i = blockIdx.x * blockDim.x + threadIdx.x;
    int4 z = make_int4(0, 0, 0, 0);
    for (; i < n4; i += gridDim.x * blockDim.x) {
        ((int4*)a)[i] = z;
        ((int4*)b)[i] = z;
    }
}

// ---------------- CSR build --------------------------------------------------
__global__ void count_kernel(const void* __restrict__ ei, int* __restrict__ cnt, int nE) {
    int i = blockIdx.x * blockDim.x + threadIdx.x;
    int is64 = g_is64;
    if (i < nE) {
        int d = load_idx(ei, (long)nE + i, is64);
        if ((unsigned)d < NODES) atomicAdd(&cnt[d], 1);
    }
}

// ---- 3-phase scan: block scans -> serial scan of partials -> add-back -------
__global__ __launch_bounds__(1024) void scan1_kernel(
    const int* __restrict__ cnt, int* __restrict__ off, int* __restrict__ part, int n)
{
    __shared__ int wsum[32];
    int tid = threadIdx.x, lane = tid & 31, wid = tid >> 5;
    int g = blockIdx.x * 1024 + tid;
    int v = (g < n) ? cnt[g] : 0;
    int s = v;
#pragma unroll
    for (int d = 1; d < 32; d <<= 1) {
        int t = __shfl_up_sync(0xffffffffu, s, d);
        if (lane >= d) s += t;
    }
    if (lane == 31) wsum[wid] = s;
    __syncthreads();
    if (wid == 0) {
        int ws = wsum[lane];
#pragma unroll
        for (int d = 1; d < 32; d <<= 1) {
            int t = __shfl_up_sync(0xffffffffu, ws, d);
            if (lane >= d) ws += t;
        }
        wsum[lane] = ws;
    }
    __syncthreads();
    int base = wid ? wsum[wid - 1] : 0;
    if (g < n) off[g] = base + s - v;       // block-local exclusive
    if (tid == 1023) part[blockIdx.x] = wsum[31];
}

__global__ void scan2_kernel(int* __restrict__ part, int nb) {
    if (threadIdx.x == 0) {
        int run = 0;
        for (int i = 0; i < nb; i++) { int t = part[i]; part[i] = run; run += t; }
        part[nb] = run;
    }
}

__global__ __launch_bounds__(1024) void scan3_kernel(
    int* __restrict__ off, const int* __restrict__ part, int n, int nb)
{
    int g = blockIdx.x * 1024 + threadIdx.x;
    if (g < n) off[g] += part[blockIdx.x];
    if (g == 0) off[n] = part[nb];
}

__global__ void fill_kernel(const void* __restrict__ ei,
                            const int* __restrict__ off, int* __restrict__ cur,
                            int* __restrict__ csr, int nE)
{
    int i = blockIdx.x * blockDim.x + threadIdx.x;
    int is64 = g_is64;
    if (i < nE) {
        int s = load_idx(ei, i, is64);
        int d = load_idx(ei, (long)nE + i, is64);
        if ((unsigned)s < NODES && (unsigned)d < NODES) {
            int pos = off[d] + atomicAdd(&cur[d], 1);
            csr[pos] = s;
        }
    }
}

// ---------------- fused SAGE layer -------------------------------------------
// out = relu( mean_{j in N(i)} feat[j] @ Wl + feat[i] @ Wr + b )      (FUSE_FC=0)
// out = (the above) @ Wfc + bfc  fused into epilogue                  (FUSE_FC=1)
//
// block: 256 thr (8 warps), 64 rows/block. Phase A: fp32 gather of neighbor
// means + root rows into smem. Phase B: dual-GEMM with packed f32x2 FMA.
template <int FUSE_FC>
__global__ __launch_bounds__(256) void sage_layer_kernel(
    const int* __restrict__ off, const int* __restrict__ csr,
    const float* __restrict__ feat,
    const float* __restrict__ Wl, const float* __restrict__ Wr,
    const float* __restrict__ bias,
    const float* __restrict__ Wfc, const float* __restrict__ bfc,
    float* __restrict__ out, int n)
{
    extern __shared__ float smem[];
    float* sAgg  = smem;                    // [64][128]
    float* sRoot = smem + 64 * F;           // [64][128]
    float* sWl   = smem + 2 * 64 * F;       // [32][128]
    float* sWr   = sWl + 32 * F;            // [32][128]
    float* sFc   = sWr + 32 * F;            // [256]

    int tid  = threadIdx.x;
    int w    = tid >> 5;
    int lane = tid & 31;
    int rowBase = blockIdx.x * 64;

    // ---------- Phase A: gather (warp w handles rows w*8 .. w*8+7) ----------
    for (int r = 0; r < 8; r++) {
        int rl = w * 8 + r;
        int row = rowBase + rl;
        float4 a0 = make_float4(0.f, 0.f, 0.f, 0.f);
        float4 a1 = make_float4(0.f, 0.f, 0.f, 0.f);
        float4 a2 = make_float4(0.f, 0.f, 0.f, 0.f);
        float4 a3 = make_float4(0.f, 0.f, 0.f, 0.f);
        float inv = 0.f;
        if (row < n) {
            int o0 = __ldg(&off[row]), o1 = __ldg(&off[row + 1]);
            int e = o0;
            for (; e + 3 < o1; e += 4) {
                int i0 = __ldg(&csr[e]);
                int i1 = __ldg(&csr[e + 1]);
                int i2 = __ldg(&csr[e + 2]);
                int i3 = __ldg(&csr[e + 3]);
                float4 v0 = ((const float4*)(feat + (long)i0 * F))[lane];
                float4 v1 = ((const float4*)(feat + (long)i1 * F))[lane];
                float4 v2 = ((const float4*)(feat + (long)i2 * F))[lane];
                float4 v3 = ((const float4*)(feat + (long)i3 * F))[lane];
                a0.x += v0.x; a0.y += v0.y; a0.z += v0.z; a0.w += v0.w;
                a1.x += v1.x; a1.y += v1.y; a1.z += v1.z; a1.w += v1.w;
                a2.x += v2.x; a2.y += v2.y; a2.z += v2.z; a2.w += v2.w;
                a3.x += v3.x; a3.y += v3.y; a3.z += v3.z; a3.w += v3.w;
            }
            for (; e < o1; e++) {
                int i0 = __ldg(&csr[e]);
                float4 v0 = ((const float4*)(feat + (long)i0 * F))[lane];
                a0.x += v0.x; a0.y += v0.y; a0.z += v0.z; a0.w += v0.w;
            }
            inv = 1.0f / fmaxf((float)(o1 - o0), 1.0f);
        }
        float4 o;
        o.x = (a0.x + a1.x + a2.x + a3.x) * inv;
        o.y = (a0.y + a1.y + a2.y + a3.y) * inv;
        o.z = (a0.z + a1.z + a2.z + a3.z) * inv;
        o.w = (a0.w + a1.w + a2.w + a3.w) * inv;
        ((float4*)&sAgg[rl * F])[lane] = o;
    }
    // root rows: 64 rows x 32 float4 = 2048 float4, 8 per thread
#pragma unroll
    for (int i = 0; i < 8; i++) {
        int idx = tid + 256 * i;
        int row = rowBase + (idx >> 5);
        int c = idx & 31;
        float4 v = make_float4(0.f, 0.f, 0.f, 0.f);
        if (row < n) v = ((const float4*)(feat + (long)row * F))[c];
        ((float4*)sRoot)[idx] = v;
    }
    if (FUSE_FC) sFc[tid] = Wfc[tid];

    // ---------- Phase B: dual-GEMM with FFMA2 --------------------------------
    unsigned long long acc01[8], acc23[8];
#pragma unroll
    for (int r = 0; r < 8; r++) { acc01[r] = 0ull; acc23[r] = 0ull; }

    for (int kt = 0; kt < 4; kt++) {
        __syncthreads();
        const float4* wl4 = (const float4*)(Wl + kt * 32 * F);
        const float4* wr4 = (const float4*)(Wr + kt * 32 * F);
#pragma unroll
        for (int i = 0; i < 4; i++) {
            ((float4*)sWl)[tid + 256 * i] = wl4[tid + 256 * i];
            ((float4*)sWr)[tid + 256 * i] = wr4[tid + 256 * i];
        }
        __syncthreads();
#pragma unroll
        for (int k = 0; k < 32; k++) {
            ulonglong2 wl = ((const ulonglong2*)(sWl + k * F))[lane];
            ulonglong2 wr = ((const ulonglong2*)(sWr + k * F))[lane];
#pragma unroll
            for (int r = 0; r < 8; r++) {
                int rl = w * 8 + r;
                unsigned ai = __float_as_uint(sAgg[rl * F + kt * 32 + k]);
                unsigned xi = __float_as_uint(sRoot[rl * F + kt * 32 + k]);
                unsigned long long a2, x2;
                asm("mov.b64 %0, {%1, %1};" : "=l"(a2) : "r"(ai));
                asm("mov.b64 %0, {%1, %1};" : "=l"(x2) : "r"(xi));
                asm("fma.rn.f32x2 %0, %1, %2, %0;" : "+l"(acc01[r]) : "l"(a2), "l"(wl.x));
                asm("fma.rn.f32x2 %0, %1, %2, %0;" : "+l"(acc23[r]) : "l"(a2), "l"(wl.y));
                asm("fma.rn.f32x2 %0, %1, %2, %0;" : "+l"(acc01[r]) : "l"(x2), "l"(wr.x));
                asm("fma.rn.f32x2 %0, %1, %2, %0;" : "+l"(acc23[r]) : "l"(x2), "l"(wr.y));
            }
        }
    }

    // ---------- epilogue -----------------------------------------------------
    float4 bv = ((const float4*)bias)[lane];
#pragma unroll
    for (int r = 0; r < 8; r++) {
        int row = rowBase + w * 8 + r;
        unsigned u0, u1, u2, u3;
        asm("mov.b64 {%0, %1}, %2;" : "=r"(u0), "=r"(u1) : "l"(acc01[r]));
        asm("mov.b64 {%0, %1}, %2;" : "=r"(u2), "=r"(u3) : "l"(acc23[r]));
        float h0 = fmaxf(__uint_as_float(u0) + bv.x, 0.f);
        float h1 = fmaxf(__uint_as_float(u1) + bv.y, 0.f);
        float h2 = fmaxf(__uint_as_float(u2) + bv.z, 0.f);
        float h3 = fmaxf(__uint_as_float(u3) + bv.w, 0.f);
        if (!FUSE_FC) {
            if (row < n) {
                float4 o; o.x = h0; o.y = h1; o.z = h2; o.w = h3;
                ((float4*)(out + (long)row * F))[lane] = o;
            }
        } else {
            int c0 = lane * 4;
            float p0 = h0 * sFc[(c0 + 0) * 2 + 0] + h1 * sFc[(c0 + 1) * 2 + 0]
                     + h2 * sFc[(c0 + 2) * 2 + 0] + h3 * sFc[(c0 + 3) * 2 + 0];
            float p1 = h0 * sFc[(c0 + 0) * 2 + 1] + h1 * sFc[(c0 + 1) * 2 + 1]
                     + h2 * sFc[(c0 + 2) * 2 + 1] + h3 * sFc[(c0 + 3) * 2 + 1];
#pragma unroll
            for (int d = 16; d > 0; d >>= 1) {
                p0 += __shfl_xor_sync(0xFFFFFFFFu, p0, d);
                p1 += __shfl_xor_sync(0xFFFFFFFFu, p1, d);
            }
            if (lane == 0 && row < n) {
                float2 o;
                o.x = p0 + __ldg(&bfc[0]);
                o.y = p1 + __ldg(&bfc[1]);
                ((float2*)out)[row] = o;
            }
        }
    }
}

// -----------------------------------------------------------------------------
extern "C" void kernel_launch(void* const* d_in, const int* in_sizes, int n_in,
                              void* d_out, int out_size)
{
    const float* x    = (const float*)d_in[0];
    const void*  ei   = d_in[1];                 // int32 or int64, auto-detected
    const float* W1l  = (const float*)d_in[2];
    const float* W1r  = (const float*)d_in[3];
    const float* b1   = (const float*)d_in[4];
    const float* W2l  = (const float*)d_in[5];
    const float* W2r  = (const float*)d_in[6];
    const float* b2   = (const float*)d_in[7];
    const float* Wfc  = (const float*)d_in[8];
    const float* bfc  = (const float*)d_in[9];
    float*       out  = (float*)d_out;

    int n  = in_sizes[0] / F;       // 50000
    int nE = in_sizes[1] / 2;       // 800000

    int *cnt, *off, *cur, *csr, *part;
    float *h1;
    cudaGetSymbolAddress((void**)&cnt,  g_cnt);
    cudaGetSymbolAddress((void**)&off,  g_off);
    cudaGetSymbolAddress((void**)&cur,  g_cur);
    cudaGetSymbolAddress((void**)&csr,  g_csr);
    cudaGetSymbolAddress((void**)&part, g_part);
    cudaGetSymbolAddress((void**)&h1,   g_h1);

    const int SMEM = (64 * F * 2 + 32 * F * 2 + 256) * 4;   // 99,328 bytes
    cudaFuncSetAttribute(sage_layer_kernel<0>,
                         cudaFuncAttributeMaxDynamicSharedMemorySize, SMEM);
    cudaFuncSetAttribute(sage_layer_kernel<1>,
                         cudaFuncAttributeMaxDynamicSharedMemorySize, SMEM);

    detect_kernel<<<1, 256>>>((const int*)ei);

    // ---- CSR build (once, reused for both layers) ----
    int nb = (n + 1023) / 1024;                 // 49
    zero2_kernel<<<32, 256>>>(cnt, cur, (n + 3) / 4);
    count_kernel<<<(nE + 255) / 256, 256>>>(ei, cnt, nE);
    scan1_kernel<<<nb, 1024>>>(cnt, off, part, n);
    scan2_kernel<<<1, 32>>>(part, nb);
    scan3_kernel<<<nb, 1024>>>(off, part, n, nb);
    fill_kernel<<<(nE + 255) / 256, 256>>>(ei, off, cur, csr, nE);

    int blocks = (n + 63) / 64;

    // ---- layer 1 (writes h1) ----
    sage_layer_kernel<0><<<blocks, 256, SMEM>>>(
        off, csr, x, W1l, W1r, b1, (const float*)0, (const float*)0, h1, n);

    // ---- layer 2 + FC head fused (writes logits) ----
    sage_layer_kernel<1><<<blocks, 256, SMEM>>>(
        off, csr, h1, W2l, W2r, b2, Wfc, bfc, out, n);
}